// round 15
// baseline (speedup 1.0000x reference)
#include <cuda_runtime.h>
#include <cuda_fp16.h>
#include <cstdint>

#define M 64
#define K 4096
#define N 11008
#define GROUP 128
#define NGROUPS 32

#define NTILE 64                 // n-cols per CTA -> 172 n-tiles
#define KSPLIT 8                 // grid (172, 8) = 1376 CTAs
#define GPB (NGROUPS / KSPLIT)   // 4 groups per CTA
#define THREADS 128              // 4 warps in 2x2: each m32 x n32

// SMEM rows padded to 272B (17 x 16B) -> ldmatrix conflict-free
#define LDA 272
#define AB(s) ((uint32_t)(s) * 17408u)              // A buf: 64 rows x 128k fp16
#define WB(s) (34816u + (uint32_t)(s) * 17408u)     // W buf: 64 n x 128k fp16
#define SMEM_BYTES 69632         // x3 CTAs = 209KB/SM

// fp16 x, k-permuted within each 8-block: [0,4,1,5,2,6,3,7]
__device__ __align__(16) __half g_xh[M * K];

// ---------------------------------------------------------------------------
// Fused prep (x -> fp16, k-permuted) + out init (bias), one launch.
// ---------------------------------------------------------------------------
#define PREP_BLOCKS 128
#define INIT_BLOCKS 688

__global__ void prep_init_kernel(const float* __restrict__ x,
                                 const float* __restrict__ bias,
                                 float* __restrict__ out) {
    const int b = blockIdx.x;
    if (b < PREP_BLOCKS) {
        int i = b * 256 + threadIdx.x;               // 0 .. 32767
        if (i >= M * (K / 8)) return;
        int m = i >> 9, blk = i & 511;
        const float* src = x + m * K + blk * 8;
        float f[8];
#pragma unroll
        for (int j = 0; j < 8; ++j) f[j] = src[j];
        const int perm[8] = {0, 4, 1, 5, 2, 6, 3, 7};
        __half h[8];
#pragma unroll
        for (int p = 0; p < 8; ++p) h[p] = __float2half(f[perm[p]]);
        *reinterpret_cast<uint4*>(g_xh + (size_t)m * K + blk * 8) =
            *reinterpret_cast<uint4*>(h);
    } else {
        int i4 = (b - PREP_BLOCKS) * 256 + threadIdx.x;
        if (i4 >= (M * N) / 4) return;
        int n = (i4 * 4) % N;                        // N % 4 == 0
        reinterpret_cast<float4*>(out)[i4] =
            *reinterpret_cast<const float4*>(bias + n);
    }
}

// ---------------------------------------------------------------------------
__device__ __forceinline__ uint32_t smem_u32(const void* p) {
    uint32_t a;
    asm("{ .reg .u64 t; cvta.to.shared.u64 t, %1; cvt.u32.u64 %0, t; }" : "=r"(a) : "l"(p));
    return a;
}
#define CP_ASYNC16_CG(dst, src) \
    asm volatile("cp.async.cg.shared.global [%0], [%1], 16;" :: "r"(dst), "l"(src) : "memory")
#define CP_COMMIT() asm volatile("cp.async.commit_group;" ::: "memory")
#define CP_WAIT0()  asm volatile("cp.async.wait_group 0;" ::: "memory")

#define LDSM_X4(r0, r1, r2, r3, a)                                              \
    asm volatile("ldmatrix.sync.aligned.m8n8.x4.shared.b16 {%0,%1,%2,%3}, [%4];" \
                 : "=r"(r0), "=r"(r1), "=r"(r2), "=r"(r3) : "r"(a))
#define MMA16816(c, a0, a1, a2, a3, b0, b1)                                     \
    asm volatile("mma.sync.aligned.m16n8k16.row.col.f32.f16.f16.f32 "           \
                 "{%0,%1,%2,%3}, {%4,%5,%6,%7}, {%8,%9}, {%0,%1,%2,%3};"        \
                 : "+f"((c)[0]), "+f"((c)[1]), "+f"((c)[2]), "+f"((c)[3])       \
                 : "r"(a0), "r"(a1), "r"(a2), "r"(a3), "r"(b0), "r"(b1))

// integer-exact (q - zero), then scale in fp16: 8 qwords -> 64 fp16 weights
__device__ __forceinline__ void dequant_store(const unsigned* q, unsigned zc2,
                                              unsigned s2, uint32_t wbase) {
#pragma unroll
    for (int j = 0; j < 8; ++j) {
        const unsigned qq = q[j];
        unsigned r0 = (qq          & 0x000F000Fu) | 0x64006400u;
        unsigned r1 = ((qq >> 4)   & 0x000F000Fu) | 0x64006400u;
        unsigned r2 = ((qq >> 8)   & 0x000F000Fu) | 0x64006400u;
        unsigned r3 = ((qq >> 12)  & 0x000F000Fu) | 0x64006400u;
        unsigned w0, w1, w2, w3;
        asm("sub.rn.f16x2 %0, %1, %2;" : "=r"(w0) : "r"(r0), "r"(zc2));
        asm("sub.rn.f16x2 %0, %1, %2;" : "=r"(w1) : "r"(r1), "r"(zc2));
        asm("sub.rn.f16x2 %0, %1, %2;" : "=r"(w2) : "r"(r2), "r"(zc2));
        asm("sub.rn.f16x2 %0, %1, %2;" : "=r"(w3) : "r"(r3), "r"(zc2));
        asm("mul.rn.f16x2 %0, %0, %1;" : "+r"(w0) : "r"(s2));
        asm("mul.rn.f16x2 %0, %0, %1;" : "+r"(w1) : "r"(s2));
        asm("mul.rn.f16x2 %0, %0, %1;" : "+r"(w2) : "r"(s2));
        asm("mul.rn.f16x2 %0, %0, %1;" : "+r"(w3) : "r"(s2));
        asm volatile("st.shared.v4.b32 [%0], {%1,%2,%3,%4};"
                     :: "r"(wbase + (uint32_t)j * 16),
                        "r"(w0), "r"(w1), "r"(w2), "r"(w3) : "memory");
    }
}

__global__ __launch_bounds__(THREADS, 3)
void gptq_mma_kernel(const int*   __restrict__ qweight,   // [K/8, N]
                     const int*   __restrict__ qzeros,    // [NGROUPS, N/8]
                     const float* __restrict__ scales,    // [NGROUPS, N]
                     float*       __restrict__ out) {
    extern __shared__ char smem[];
    const uint32_t sb = smem_u32(smem);
    const int tid  = threadIdx.x;
    const int wid  = tid >> 5;
    const int lane = tid & 31;
    const int tig  = lane & 3;
    const int nb0  = blockIdx.x * NTILE;
    const int g0   = blockIdx.y * GPB;

    // warp tile: 2x2 over m64 x n64 -> each warp m32 x n32
    const int mrow = wid & 1;
    const int ncol = wid >> 1;

    // dequant role: column + qrow half
    const int nloc   = tid & 63;
    const int nG     = nb0 + nloc;
    const int qrhalf = tid >> 6;                   // 0/1 -> qrows 0-7 / 8-15
    const uint32_t wlaneOff = (uint32_t)nloc * LDA + (uint32_t)qrhalf * 128u;

    // ldmatrix lane offsets
    const int rowA  = lane & 15;
    const uint32_t aLane = (uint32_t)rowA * LDA + ((lane >> 4) << 4);
    const int nrowB = (lane & 7) | ((lane >> 1) & 8);
    const uint32_t bHalf = (lane & 8) ? 16u : 0u;

    const uint32_t aOff0 = (uint32_t)(mrow * 32 + 0)  * LDA + aLane;
    const uint32_t aOff1 = (uint32_t)(mrow * 32 + 16) * LDA + aLane;
    const uint32_t wOff0 = (uint32_t)(ncol * 32 + 0  + nrowB) * LDA + bHalf;
    const uint32_t wOff1 = (uint32_t)(ncol * 32 + 16 + nrowB) * LDA + bHalf;

    const int nbase = nb0 + ncol * 32 + 2 * tig;

    float P[2][4][4];
#pragma unroll
    for (int mt = 0; mt < 2; ++mt)
#pragma unroll
        for (int c = 0; c < 4; ++c)
#pragma unroll
            for (int j = 0; j < 4; ++j) P[mt][c][j] = 0.f;

    // ---- helpers -----------------------------------------------------------
    auto stageA = [&](int g, int s) {
        const int kg0 = g * GROUP;
#pragma unroll
        for (int p = 0; p < 8; ++p) {
            int idx = p * THREADS + tid;           // 1024 16B chunks
            int row = idx >> 4, ch = idx & 15;
            const void* src = g_xh + (size_t)row * K + kg0 + ch * 8;
            CP_ASYNC16_CG(sb + AB(s) + (uint32_t)row * LDA + (uint32_t)ch * 16, src);
        }
        CP_COMMIT();
    };
    auto loadQ = [&](int g, unsigned* q) {
        const int qrow0 = ((g * GROUP) >> 3) + qrhalf * 8;
#pragma unroll
        for (int j = 0; j < 8; ++j)
            q[j] = (unsigned)__ldcg(&qweight[(size_t)(qrow0 + j) * N + nG]);
    };
    auto makeZ = [&](unsigned zw) -> unsigned {
        const unsigned zc = 0x6400u + ((zw >> (4 * (nG & 7))) & 15u) + 1u;
        return zc | (zc << 16);
    };
    auto makeS = [&](float sf) -> unsigned {
        __half2 sh = __float2half2_rn(sf);
        return *reinterpret_cast<unsigned*>(&sh);
    };

    // ---- prologue: fill buffers for group g0 -------------------------------
    {
        stageA(g0, 0);
        unsigned q[8];
        loadQ(g0, q);
        const unsigned zw = (unsigned)__ldcg(&qzeros[g0 * (N / 8) + (nG >> 3)]);
        const float sf = __ldcg(&scales[(size_t)g0 * N + nG]);
        dequant_store(q, makeZ(zw), makeS(sf), sb + WB(0) + wlaneOff);
        CP_WAIT0();
        __syncthreads();
    }

#pragma unroll 1
    for (int gi = 0; gi < GPB; ++gi) {
        const int g    = g0 + gi;
        const int cur  = gi & 1;
        const bool more = (gi + 1) < GPB;

        // ---- issue next group's loads (land under the mma) ------------------
        unsigned nq[8], nzw = 0;
        float nsf = 0.f;
        if (more) {
            stageA(g + 1, cur ^ 1);
            loadQ(g + 1, nq);
            nzw = (unsigned)__ldcg(&qzeros[(g + 1) * (N / 8) + (nG >> 3)]);
            nsf = __ldcg(&scales[(size_t)(g + 1) * N + nG]);
        }

        // ---- compute: 8 k16 steps on buffers[cur] ---------------------------
        const uint32_t aBase = sb + AB(cur);
        const uint32_t wBase = sb + WB(cur);
#pragma unroll 1
        for (int st = 0; st < 8; ++st) {
            const uint32_t so = (uint32_t)st * 32;
            uint32_t b00, b01, b02, b03, b10, b11, b12, b13;
            LDSM_X4(b00, b01, b02, b03, wBase + wOff0 + so);
            LDSM_X4(b10, b11, b12, b13, wBase + wOff1 + so);
#pragma unroll
            for (int mt = 0; mt < 2; ++mt) {
                uint32_t a0, a1, a2, a3;
                LDSM_X4(a0, a1, a2, a3, aBase + (mt ? aOff1 : aOff0) + so);
                MMA16816(P[mt][0], a0, a1, a2, a3, b00, b01);
                MMA16816(P[mt][1], a0, a1, a2, a3, b02, b03);
                MMA16816(P[mt][2], a0, a1, a2, a3, b10, b11);
                MMA16816(P[mt][3], a0, a1, a2, a3, b12, b13);
            }
        }

        // ---- build next group's W from prefetched regs, retire cp.async -----
        if (more) {
            dequant_store(nq, makeZ(nzw), makeS(nsf), sb + WB(cur ^ 1) + wlaneOff);
            CP_WAIT0();
        }
        __syncthreads();
    }

    // ---- epilogue: accumulate into bias-initialized out ---------------------
    {
        const int r = lane >> 2;
#pragma unroll
        for (int mt = 0; mt < 2; ++mt) {
            const int m0 = mrow * 32 + mt * 16 + r;
#pragma unroll
            for (int c = 0; c < 4; ++c) {
                const int n = nbase + c * 8;
                atomicAdd(&out[(size_t)m0 * N + n],           P[mt][c][0]);
                atomicAdd(&out[(size_t)m0 * N + n + 1],       P[mt][c][1]);
                atomicAdd(&out[(size_t)(m0 + 8) * N + n],     P[mt][c][2]);
                atomicAdd(&out[(size_t)(m0 + 8) * N + n + 1], P[mt][c][3]);
            }
        }
    }
}

// ---------------------------------------------------------------------------
// kernel_launch: inputs per metadata order: x, qweight, qzeros, scales, bias
// ---------------------------------------------------------------------------
extern "C" void kernel_launch(void* const* d_in, const int* in_sizes, int n_in,
                              void* d_out, int out_size) {
    (void)in_sizes; (void)n_in; (void)out_size;
    const float* x       = (const float*)d_in[0];
    const int*   qweight = (const int*)  d_in[1];
    const int*   qzeros  = (const int*)  d_in[2];
    const float* scales  = (const float*)d_in[3];
    const float* bias    = (const float*)d_in[4];
    float*       out     = (float*)d_out;

    cudaFuncSetAttribute(gptq_mma_kernel,
                         cudaFuncAttributeMaxDynamicSharedMemorySize, SMEM_BYTES);

    prep_init_kernel<<<PREP_BLOCKS + INIT_BLOCKS, 256>>>(x, bias, out);

    dim3 grid(N / NTILE, KSPLIT);               // (172, 8)
    gptq_mma_kernel<<<grid, THREADS, SMEM_BYTES>>>(qweight, qzeros, scales, out);
}

// round 16
// speedup vs baseline: 1.1405x; 1.1405x over previous
#include <cuda_runtime.h>
#include <cuda_fp16.h>
#include <cstdint>

#define M 64
#define K 4096
#define N 11008
#define GROUP 128
#define NGROUPS 32

#define NTILE 128                // n-cols per CTA -> 86 n-tiles
#define KSPLIT 8                 // grid (86, 8) = 688 CTAs
#define GPB (NGROUPS / KSPLIT)   // 4 groups per CTA
#define THREADS 128              // 4 warps in 2x2: each m32 x n64

// SMEM rows padded to 272B (17 x 16B) -> ldmatrix conflict-free
#define LDA 272
#define A_OFF 0                  // A: 64 rows x 128 k fp16 = 17408B
#define W_OFF 17408              // W: 128 n x 128 k fp16 = 34816B
#define SMEM_BYTES 52224         // x4 CTAs = 204KB/SM

// fp16 x, k-permuted within each 8-block: [0,4,1,5,2,6,3,7]
__device__ __align__(16) __half g_xh[M * K];

// ---------------------------------------------------------------------------
// Fused prep (x -> fp16, k-permuted) + out init (bias), one launch.
// ---------------------------------------------------------------------------
#define PREP_BLOCKS 128
#define INIT_BLOCKS 688

__global__ void prep_init_kernel(const float* __restrict__ x,
                                 const float* __restrict__ bias,
                                 float* __restrict__ out) {
    const int b = blockIdx.x;
    if (b < PREP_BLOCKS) {
        int i = b * 256 + threadIdx.x;               // 0 .. 32767
        if (i >= M * (K / 8)) return;
        int m = i >> 9, blk = i & 511;
        const float* src = x + m * K + blk * 8;
        float f[8];
#pragma unroll
        for (int j = 0; j < 8; ++j) f[j] = src[j];
        const int perm[8] = {0, 4, 1, 5, 2, 6, 3, 7};
        __half h[8];
#pragma unroll
        for (int p = 0; p < 8; ++p) h[p] = __float2half(f[perm[p]]);
        *reinterpret_cast<uint4*>(g_xh + (size_t)m * K + blk * 8) =
            *reinterpret_cast<uint4*>(h);
    } else {
        int i4 = (b - PREP_BLOCKS) * 256 + threadIdx.x;
        if (i4 >= (M * N) / 4) return;
        int n = (i4 * 4) % N;                        // N % 4 == 0
        reinterpret_cast<float4*>(out)[i4] =
            *reinterpret_cast<const float4*>(bias + n);
    }
}

// ---------------------------------------------------------------------------
__device__ __forceinline__ uint32_t smem_u32(const void* p) {
    uint32_t a;
    asm("{ .reg .u64 t; cvta.to.shared.u64 t, %1; cvt.u32.u64 %0, t; }" : "=r"(a) : "l"(p));
    return a;
}
#define CP_ASYNC16_CG(dst, src) \
    asm volatile("cp.async.cg.shared.global [%0], [%1], 16;" :: "r"(dst), "l"(src) : "memory")
#define CP_COMMIT() asm volatile("cp.async.commit_group;" ::: "memory")
#define CP_WAIT0()  asm volatile("cp.async.wait_group 0;" ::: "memory")
#define PREFETCH_L2(p) asm volatile("prefetch.global.L2 [%0];" :: "l"(p))

#define LDSM_X4(r0, r1, r2, r3, a)                                              \
    asm volatile("ldmatrix.sync.aligned.m8n8.x4.shared.b16 {%0,%1,%2,%3}, [%4];" \
                 : "=r"(r0), "=r"(r1), "=r"(r2), "=r"(r3) : "r"(a))
#define MMA16816(c, a0, a1, a2, a3, b0, b1)                                     \
    asm volatile("mma.sync.aligned.m16n8k16.row.col.f32.f16.f16.f32 "           \
                 "{%0,%1,%2,%3}, {%4,%5,%6,%7}, {%8,%9}, {%0,%1,%2,%3};"        \
                 : "+f"((c)[0]), "+f"((c)[1]), "+f"((c)[2]), "+f"((c)[3])       \
                 : "r"(a0), "r"(a1), "r"(a2), "r"(a3), "r"(b0), "r"(b1))

__global__ __launch_bounds__(THREADS, 4)
void gptq_mma_kernel(const int*   __restrict__ qweight,   // [K/8, N]
                     const int*   __restrict__ qzeros,    // [NGROUPS, N/8]
                     const float* __restrict__ scales,    // [NGROUPS, N]
                     float*       __restrict__ out) {
    extern __shared__ char smem[];
    const uint32_t sb = smem_u32(smem);
    const int tid  = threadIdx.x;
    const int wid  = tid >> 5;
    const int lane = tid & 31;
    const int tig  = lane & 3;
    const int nb0  = blockIdx.x * NTILE;
    const int g0   = blockIdx.y * GPB;

    // warp tile: 2x2 over m64 x n128 -> each warp m32 x n64
    const int mrow = wid & 1;
    const int ncol = wid >> 1;

    // dequant role: one n-column per thread, all 16 qrows
    const int nG = nb0 + tid;
    const uint32_t wlane = sb + W_OFF + (uint32_t)tid * LDA;

    // ldmatrix lane offsets
    const int rowA  = lane & 15;
    const uint32_t aLane = (uint32_t)rowA * LDA + ((lane >> 4) << 4);
    const int nrowB = (lane & 7) | ((lane >> 1) & 8);
    const uint32_t bHalf = (lane & 8) ? 16u : 0u;

    const uint32_t aB[2] = {
        sb + A_OFF + (uint32_t)(mrow * 32 + 0)  * LDA + aLane,
        sb + A_OFF + (uint32_t)(mrow * 32 + 16) * LDA + aLane };
    uint32_t wB[4];
#pragma unroll
    for (int bq = 0; bq < 4; ++bq)
        wB[bq] = sb + W_OFF + (uint32_t)(ncol * 64 + bq * 16 + nrowB) * LDA + bHalf;

    const int nbase = nb0 + ncol * 64 + 2 * tig;

    float P[2][8][4];                              // [mt][n8 chunk][frag]
#pragma unroll
    for (int mt = 0; mt < 2; ++mt)
#pragma unroll
        for (int c = 0; c < 8; ++c)
#pragma unroll
            for (int j = 0; j < 4; ++j) P[mt][c][j] = 0.f;

#pragma unroll 1
    for (int gi = 0; gi < GPB; ++gi) {
        const int g   = g0 + gi;
        const int kg0 = g * GROUP;

        __syncthreads();                           // smem reuse barrier

        // ---- stage A via cp.async.cg: 64 rows x 128 k fp16 (8 chunks/thread)
#pragma unroll
        for (int p = 0; p < 8; ++p) {
            int idx = p * THREADS + tid;           // 1024 16B chunks
            int row = idx >> 4, ch = idx & 15;
            const void* src = g_xh + (size_t)row * K + kg0 + ch * 8;
            CP_ASYNC16_CG(sb + A_OFF + (uint32_t)row * LDA + (uint32_t)ch * 16, src);
        }
        CP_COMMIT();

        // ---- dequant W: this thread's column, 16 qrows, scale folded --------
        {
            const unsigned zw = (unsigned)__ldcg(&qzeros[g * (N / 8) + (nG >> 3)]);
            const unsigned zc = 0x6400u + ((zw >> (4 * (nG & 7))) & 15u) + 1u;
            const unsigned zc2 = zc | (zc << 16);
            const float sf = __ldcg(&scales[(size_t)g * N + nG]);
            __half2 sh = __float2half2_rn(sf);
            const unsigned s2 = *reinterpret_cast<unsigned*>(&sh);
            const int qrow0 = kg0 >> 3;
#pragma unroll
            for (int j = 0; j < 16; ++j) {
                const unsigned q = (unsigned)__ldcg(&qweight[(size_t)(qrow0 + j) * N + nG]);
                unsigned r0 = (q          & 0x000F000Fu) | 0x64006400u;
                unsigned r1 = ((q >> 4)   & 0x000F000Fu) | 0x64006400u;
                unsigned r2 = ((q >> 8)   & 0x000F000Fu) | 0x64006400u;
                unsigned r3 = ((q >> 12)  & 0x000F000Fu) | 0x64006400u;
                unsigned w0, w1, w2, w3;
                asm("sub.rn.f16x2 %0, %1, %2;" : "=r"(w0) : "r"(r0), "r"(zc2));
                asm("sub.rn.f16x2 %0, %1, %2;" : "=r"(w1) : "r"(r1), "r"(zc2));
                asm("sub.rn.f16x2 %0, %1, %2;" : "=r"(w2) : "r"(r2), "r"(zc2));
                asm("sub.rn.f16x2 %0, %1, %2;" : "=r"(w3) : "r"(r3), "r"(zc2));
                asm("mul.rn.f16x2 %0, %0, %1;" : "+r"(w0) : "r"(s2));
                asm("mul.rn.f16x2 %0, %0, %1;" : "+r"(w1) : "r"(s2));
                asm("mul.rn.f16x2 %0, %0, %1;" : "+r"(w2) : "r"(s2));
                asm("mul.rn.f16x2 %0, %0, %1;" : "+r"(w3) : "r"(s2));
                asm volatile("st.shared.v4.b32 [%0], {%1,%2,%3,%4};"
                             :: "r"(wlane + (uint32_t)j * 16),
                                "r"(w0), "r"(w1), "r"(w2), "r"(w3) : "memory");
            }
        }

        // ---- L2-prefetch NEXT group's weights/zeros/scales ------------------
        if (gi + 1 < GPB) {
            const int gn     = g + 1;
            const int qrow0n = (gn * GROUP) >> 3;
#pragma unroll
            for (int j = 0; j < 16; ++j)
                PREFETCH_L2(&qweight[(size_t)(qrow0n + j) * N + nG]);
            PREFETCH_L2(&qzeros[gn * (N / 8) + (nG >> 3)]);
            PREFETCH_L2(&scales[(size_t)gn * N + nG]);
        }

        CP_WAIT0();
        __syncthreads();

        // ---- compute: 8 k16 steps, 6 LDSM + 16 HMMA each --------------------
#pragma unroll 1
        for (int st = 0; st < 8; ++st) {
            const uint32_t so = (uint32_t)st * 32;
            uint32_t B[4][4];
#pragma unroll
            for (int bq = 0; bq < 4; ++bq)
                LDSM_X4(B[bq][0], B[bq][1], B[bq][2], B[bq][3], wB[bq] + so);
#pragma unroll
            for (int mt = 0; mt < 2; ++mt) {
                uint32_t a0, a1, a2, a3;
                LDSM_X4(a0, a1, a2, a3, aB[mt] + so);
#pragma unroll
                for (int bq = 0; bq < 4; ++bq) {
                    MMA16816(P[mt][2 * bq],     a0, a1, a2, a3, B[bq][0], B[bq][1]);
                    MMA16816(P[mt][2 * bq + 1], a0, a1, a2, a3, B[bq][2], B[bq][3]);
                }
            }
        }
    }

    // ---- epilogue: accumulate into bias-initialized out ---------------------
    {
        const int r = lane >> 2;
#pragma unroll
        for (int mt = 0; mt < 2; ++mt) {
            const int m0 = mrow * 32 + mt * 16 + r;
#pragma unroll
            for (int c = 0; c < 8; ++c) {
                const int n = nbase + (c >> 1) * 16 + (c & 1) * 8;
                atomicAdd(&out[(size_t)m0 * N + n],           P[mt][c][0]);
                atomicAdd(&out[(size_t)m0 * N + n + 1],       P[mt][c][1]);
                atomicAdd(&out[(size_t)(m0 + 8) * N + n],     P[mt][c][2]);
                atomicAdd(&out[(size_t)(m0 + 8) * N + n + 1], P[mt][c][3]);
            }
        }
    }
}

// ---------------------------------------------------------------------------
// kernel_launch: inputs per metadata order: x, qweight, qzeros, scales, bias
// ---------------------------------------------------------------------------
extern "C" void kernel_launch(void* const* d_in, const int* in_sizes, int n_in,
                              void* d_out, int out_size) {
    (void)in_sizes; (void)n_in; (void)out_size;
    const float* x       = (const float*)d_in[0];
    const int*   qweight = (const int*)  d_in[1];
    const int*   qzeros  = (const int*)  d_in[2];
    const float* scales  = (const float*)d_in[3];
    const float* bias    = (const float*)d_in[4];
    float*       out     = (float*)d_out;

    cudaFuncSetAttribute(gptq_mma_kernel,
                         cudaFuncAttributeMaxDynamicSharedMemorySize, SMEM_BYTES);

    prep_init_kernel<<<PREP_BLOCKS + INIT_BLOCKS, 256>>>(x, bias, out);

    dim3 grid(N / NTILE, KSPLIT);               // (86, 8)
    gptq_mma_kernel<<<grid, THREADS, SMEM_BYTES>>>(qweight, qzeros, scales, out);
}

// round 17
// speedup vs baseline: 1.1880x; 1.0417x over previous
#include <cuda_runtime.h>
#include <cuda_fp16.h>
#include <cstdint>

#define M 64
#define K 4096
#define N 11008
#define GROUP 128
#define NGROUPS 32

#define NTILE 128                // n-cols per CTA -> 86 n-tiles
#define KSPLIT 8                 // grid (86, 8) = 688 CTAs
#define GPB (NGROUPS / KSPLIT)   // 4 groups per CTA
#define THREADS 256              // warps 0-3: mma consumers, 4-7: producers

// SMEM rows padded to 272B (17 x 16B) -> ldmatrix conflict-free
#define LDA 272
// Double-buffered: A[s] 64x128k fp16 (17408B), W[s] 128x128k fp16 (34816B)
#define AB(s) ((uint32_t)(s) * 17408u)
#define WB(s) (34816u + (uint32_t)(s) * 34816u)
#define SMEM_BYTES 104448        // x2 CTAs = 209KB/SM

// Named barriers: full[s] = 1+s, empty[s] = 3+s
#define BAR_SYNC(id)   asm volatile("bar.sync %0, 256;"   :: "r"(id) : "memory")
#define BAR_ARRIVE(id) asm volatile("bar.arrive %0, 256;" :: "r"(id) : "memory")

// fp16 x, k-permuted within each 8-block: [0,4,1,5,2,6,3,7]
__device__ __align__(16) __half g_xh[M * K];

// ---------------------------------------------------------------------------
// Fused prep (x -> fp16, k-permuted) + out init (bias), one launch.
// ---------------------------------------------------------------------------
#define PREP_BLOCKS 128
#define INIT_BLOCKS 688

__global__ void prep_init_kernel(const float* __restrict__ x,
                                 const float* __restrict__ bias,
                                 float* __restrict__ out) {
    const int b = blockIdx.x;
    if (b < PREP_BLOCKS) {
        int i = b * 256 + threadIdx.x;               // 0 .. 32767
        if (i >= M * (K / 8)) return;
        int m = i >> 9, blk = i & 511;
        const float* src = x + m * K + blk * 8;
        float f[8];
#pragma unroll
        for (int j = 0; j < 8; ++j) f[j] = src[j];
        const int perm[8] = {0, 4, 1, 5, 2, 6, 3, 7};
        __half h[8];
#pragma unroll
        for (int p = 0; p < 8; ++p) h[p] = __float2half(f[perm[p]]);
        *reinterpret_cast<uint4*>(g_xh + (size_t)m * K + blk * 8) =
            *reinterpret_cast<uint4*>(h);
    } else {
        int i4 = (b - PREP_BLOCKS) * 256 + threadIdx.x;
        if (i4 >= (M * N) / 4) return;
        int n = (i4 * 4) % N;                        // N % 4 == 0
        reinterpret_cast<float4*>(out)[i4] =
            *reinterpret_cast<const float4*>(bias + n);
    }
}

// ---------------------------------------------------------------------------
__device__ __forceinline__ uint32_t smem_u32(const void* p) {
    uint32_t a;
    asm("{ .reg .u64 t; cvta.to.shared.u64 t, %1; cvt.u32.u64 %0, t; }" : "=r"(a) : "l"(p));
    return a;
}
#define CP_ASYNC16_CG(dst, src) \
    asm volatile("cp.async.cg.shared.global [%0], [%1], 16;" :: "r"(dst), "l"(src) : "memory")
#define CP_COMMIT() asm volatile("cp.async.commit_group;" ::: "memory")
#define CP_WAIT0()  asm volatile("cp.async.wait_group 0;" ::: "memory")

#define LDSM_X4(r0, r1, r2, r3, a)                                              \
    asm volatile("ldmatrix.sync.aligned.m8n8.x4.shared.b16 {%0,%1,%2,%3}, [%4];" \
                 : "=r"(r0), "=r"(r1), "=r"(r2), "=r"(r3) : "r"(a))
#define MMA16816(c, a0, a1, a2, a3, b0, b1)                                     \
    asm volatile("mma.sync.aligned.m16n8k16.row.col.f32.f16.f16.f32 "           \
                 "{%0,%1,%2,%3}, {%4,%5,%6,%7}, {%8,%9}, {%0,%1,%2,%3};"        \
                 : "+f"((c)[0]), "+f"((c)[1]), "+f"((c)[2]), "+f"((c)[3])       \
                 : "r"(a0), "r"(a1), "r"(a2), "r"(a3), "r"(b0), "r"(b1))

__global__ __launch_bounds__(THREADS, 2)
void gptq_mma_kernel(const int*   __restrict__ qweight,   // [K/8, N]
                     const int*   __restrict__ qzeros,    // [NGROUPS, N/8]
                     const float* __restrict__ scales,    // [NGROUPS, N]
                     float*       __restrict__ out) {
    extern __shared__ char smem[];
    const uint32_t sb = smem_u32(smem);
    const int tid  = threadIdx.x;
    const int wid  = tid >> 5;
    const int lane = tid & 31;
    const int nb0  = blockIdx.x * NTILE;
    const int g0   = blockIdx.y * GPB;

    if (wid < 4) {
        // ================= CONSUMER: 4 warps, 2x2 over m64 x n128 ============
        const int tig  = lane & 3;
        const int mrow = wid & 1;
        const int ncol = wid >> 1;

        const int rowA  = lane & 15;
        const uint32_t aLane = (uint32_t)rowA * LDA + ((lane >> 4) << 4);
        const int nrowB = (lane & 7) | ((lane >> 1) & 8);
        const uint32_t bHalf = (lane & 8) ? 16u : 0u;

        const uint32_t aOff[2] = {
            (uint32_t)(mrow * 32 + 0)  * LDA + aLane,
            (uint32_t)(mrow * 32 + 16) * LDA + aLane };
        uint32_t wOff[4];
#pragma unroll
        for (int bq = 0; bq < 4; ++bq)
            wOff[bq] = (uint32_t)(ncol * 64 + bq * 16 + nrowB) * LDA + bHalf;

        const int nbase = nb0 + ncol * 64 + 2 * tig;

        float P[2][8][4];
#pragma unroll
        for (int mt = 0; mt < 2; ++mt)
#pragma unroll
            for (int c = 0; c < 8; ++c)
#pragma unroll
                for (int j = 0; j < 4; ++j) P[mt][c][j] = 0.f;

#pragma unroll 1
        for (int gi = 0; gi < GPB; ++gi) {
            const int s = gi & 1;
            BAR_SYNC(1 + s);                       // wait full[s]

            const uint32_t aBase = sb + AB(s);
            const uint32_t wBase = sb + WB(s);
#pragma unroll 1
            for (int st = 0; st < 8; ++st) {
                const uint32_t so = (uint32_t)st * 32;
                uint32_t B[4][4];
#pragma unroll
                for (int bq = 0; bq < 4; ++bq)
                    LDSM_X4(B[bq][0], B[bq][1], B[bq][2], B[bq][3],
                            wBase + wOff[bq] + so);
#pragma unroll
                for (int mt = 0; mt < 2; ++mt) {
                    uint32_t a0, a1, a2, a3;
                    LDSM_X4(a0, a1, a2, a3, aBase + aOff[mt] + so);
#pragma unroll
                    for (int bq = 0; bq < 4; ++bq) {
                        MMA16816(P[mt][2 * bq],     a0, a1, a2, a3, B[bq][0], B[bq][1]);
                        MMA16816(P[mt][2 * bq + 1], a0, a1, a2, a3, B[bq][2], B[bq][3]);
                    }
                }
            }
            BAR_ARRIVE(3 + s);                     // signal empty[s]
        }

        // ---- epilogue: accumulate into bias-initialized out ------------------
        const int r = lane >> 2;
#pragma unroll
        for (int mt = 0; mt < 2; ++mt) {
            const int m0 = mrow * 32 + mt * 16 + r;
#pragma unroll
            for (int c = 0; c < 8; ++c) {
                const int n = nbase + (c >> 1) * 16 + (c & 1) * 8;
                atomicAdd(&out[(size_t)m0 * N + n],           P[mt][c][0]);
                atomicAdd(&out[(size_t)m0 * N + n + 1],       P[mt][c][1]);
                atomicAdd(&out[(size_t)(m0 + 8) * N + n],     P[mt][c][2]);
                atomicAdd(&out[(size_t)(m0 + 8) * N + n + 1], P[mt][c][3]);
            }
        }
    } else {
        // ================= PRODUCER: 4 warps, staging + dequant ==============
        const int tid2 = tid & 127;                // 0..127
        const int nG   = nb0 + tid2;               // this thread's n-column

#pragma unroll 1
        for (int gi = 0; gi < GPB; ++gi) {
            const int s   = gi & 1;
            const int g   = g0 + gi;
            const int kg0 = g * GROUP;

            if (gi >= 2) BAR_SYNC(3 + s);          // wait empty[s]

            // ---- stage A via cp.async.cg: 8 chunks/thread -------------------
#pragma unroll
            for (int p = 0; p < 8; ++p) {
                int idx = p * 128 + tid2;          // 1024 16B chunks
                int row = idx >> 4, ch = idx & 15;
                const void* src = g_xh + (size_t)row * K + kg0 + ch * 8;
                CP_ASYNC16_CG(sb + AB(s) + (uint32_t)row * LDA + (uint32_t)ch * 16, src);
            }
            CP_COMMIT();

            // ---- dequant W: 1 column x 16 qrows, scale folded ---------------
            {
                const unsigned zw = (unsigned)__ldcg(&qzeros[g * (N / 8) + (nG >> 3)]);
                const unsigned zc = 0x6400u + ((zw >> (4 * (nG & 7))) & 15u) + 1u;
                const unsigned zc2 = zc | (zc << 16);
                const float sf = __ldcg(&scales[(size_t)g * N + nG]);
                __half2 sh = __float2half2_rn(sf);
                const unsigned s2 = *reinterpret_cast<unsigned*>(&sh);
                const int qrow0 = kg0 >> 3;
                const uint32_t wlane = sb + WB(s) + (uint32_t)tid2 * LDA;
#pragma unroll
                for (int j = 0; j < 16; ++j) {
                    const unsigned q = (unsigned)__ldcg(&qweight[(size_t)(qrow0 + j) * N + nG]);
                    unsigned r0 = (q          & 0x000F000Fu) | 0x64006400u;
                    unsigned r1 = ((q >> 4)   & 0x000F000Fu) | 0x64006400u;
                    unsigned r2 = ((q >> 8)   & 0x000F000Fu) | 0x64006400u;
                    unsigned r3 = ((q >> 12)  & 0x000F000Fu) | 0x64006400u;
                    unsigned w0, w1, w2, w3;
                    asm("sub.rn.f16x2 %0, %1, %2;" : "=r"(w0) : "r"(r0), "r"(zc2));
                    asm("sub.rn.f16x2 %0, %1, %2;" : "=r"(w1) : "r"(r1), "r"(zc2));
                    asm("sub.rn.f16x2 %0, %1, %2;" : "=r"(w2) : "r"(r2), "r"(zc2));
                    asm("sub.rn.f16x2 %0, %1, %2;" : "=r"(w3) : "r"(r3), "r"(zc2));
                    asm("mul.rn.f16x2 %0, %0, %1;" : "+r"(w0) : "r"(s2));
                    asm("mul.rn.f16x2 %0, %0, %1;" : "+r"(w1) : "r"(s2));
                    asm("mul.rn.f16x2 %0, %0, %1;" : "+r"(w2) : "r"(s2));
                    asm("mul.rn.f16x2 %0, %0, %1;" : "+r"(w3) : "r"(s2));
                    asm volatile("st.shared.v4.b32 [%0], {%1,%2,%3,%4};"
                                 :: "r"(wlane + (uint32_t)j * 16),
                                    "r"(w0), "r"(w1), "r"(w2), "r"(w3) : "memory");
                }
            }

            CP_WAIT0();                            // A landed
            BAR_ARRIVE(1 + s);                     // signal full[s]
        }
    }
}

// ---------------------------------------------------------------------------
// kernel_launch: inputs per metadata order: x, qweight, qzeros, scales, bias
// ---------------------------------------------------------------------------
extern "C" void kernel_launch(void* const* d_in, const int* in_sizes, int n_in,
                              void* d_out, int out_size) {
    (void)in_sizes; (void)n_in; (void)out_size;
    const float* x       = (const float*)d_in[0];
    const int*   qweight = (const int*)  d_in[1];
    const int*   qzeros  = (const int*)  d_in[2];
    const float* scales  = (const float*)d_in[3];
    const float* bias    = (const float*)d_in[4];
    float*       out     = (float*)d_out;

    cudaFuncSetAttribute(gptq_mma_kernel,
                         cudaFuncAttributeMaxDynamicSharedMemorySize, SMEM_BYTES);

    prep_init_kernel<<<PREP_BLOCKS + INIT_BLOCKS, 256>>>(x, bias, out);

    dim3 grid(N / NTILE, KSPLIT);               // (86, 8)
    gptq_mma_kernel<<<grid, THREADS, SMEM_BYTES>>>(qweight, qzeros, scales, out);
}